// round 13
// baseline (speedup 1.0000x reference)
#include <cuda_runtime.h>
#include <cuda_fp16.h>
#include <cstdint>

// ---------------------------------------------------------------------------
// out[t,o] = sum_i (x[t,i]*scales[i]) * W[o,i]
//   x [32,4096] f32, W [14336,4096] int32 (int8-valued), scales [4096] f32
//   out [32,14336] f32
//
// R12: fp16 HMMA, NO split-K (direct stores, no atomics/zeroing), TILE_M=32,
// KC=128 -> 512B contiguous DRAM run per weight row per chunk (R11 had 256B;
// DRAM ceiling ~70% suspected page-locality). 448 CTAs (balanced), NITER=32,
// tiles stored as two 128B-row subtiles so SW128 math is unchanged.
// 16x16 warp tiling, depth-1 named W staging, double buffer, 1 barrier/chunk.
// ---------------------------------------------------------------------------

#define SWZ(off) ((off) ^ (((off) >> 3) & 0x70))

static constexpr int TOKENS = 32;
static constexpr int INF    = 4096;
static constexpr int OUTF   = 14336;
static constexpr int TILE_M = 32;
static constexpr int NTHR   = 128;
static constexpr int KC     = 128;              // K elements per chunk
static constexpr int NITER  = INF / KC;         // 32

// per-buffer SMEM layout (bytes); subtile s at +s*4096 (rows of 128B, SW128)
static constexpr int X_OFF      = 8192;              // W: 2 subtiles x 4KB
static constexpr int BUF_BYTES  = 16384;             // + xs: 2 subtiles x 4KB
static constexpr int SMEM_TOTAL = 2 * BUF_BYTES;     // 32768

// fp16 scaled activations (built by prep kernel)
__device__ __align__(16) __half g_xs[TOKENS * INF];

// ---------------- helpers ----------------
__device__ __forceinline__ uint32_t smem_u32(const void* p) {
    uint32_t a;
    asm("{ .reg .u64 t; cvta.to.shared.u64 t, %1; cvt.u32.u64 %0, t; }"
        : "=r"(a) : "l"(p));
    return a;
}

__device__ __forceinline__ void sts128(uint32_t addr, uint32_t r0, uint32_t r1,
                                       uint32_t r2, uint32_t r3) {
    asm volatile("st.shared.v4.b32 [%0], {%1, %2, %3, %4};"
                 :: "r"(addr), "r"(r0), "r"(r1), "r"(r2), "r"(r3) : "memory");
}

__device__ __forceinline__ void cp16(uint32_t dst, const void* src) {
    asm volatile("cp.async.cg.shared.global [%0], [%1], 16;"
                 :: "r"(dst), "l"(src) : "memory");
}
__device__ __forceinline__ void cp_commit() {
    asm volatile("cp.async.commit_group;" ::: "memory");
}
__device__ __forceinline__ void cp_wait0() {
    asm volatile("cp.async.wait_group 0;" ::: "memory");
}

// pack two ints (|v|<=127, exact in fp16) -> half2 bits
__device__ __forceinline__ uint32_t packhf(int a, int b) {
    __half2 h = __floats2half2_rn((float)a, (float)b);
    return *reinterpret_cast<uint32_t*>(&h);
}

__device__ __forceinline__ void ldsm_x4(uint32_t addr, uint32_t& r0, uint32_t& r1,
                                        uint32_t& r2, uint32_t& r3) {
    asm volatile("ldmatrix.sync.aligned.m8n8.x4.shared.b16 {%0,%1,%2,%3}, [%4];"
                 : "=r"(r0), "=r"(r1), "=r"(r2), "=r"(r3) : "r"(addr));
}

__device__ __forceinline__ void mma_16816(float* d, const uint32_t* a, const uint32_t* b) {
    asm volatile(
        "mma.sync.aligned.m16n8k16.row.col.f32.f16.f16.f32 "
        "{%0,%1,%2,%3}, {%4,%5,%6,%7}, {%8,%9}, {%0,%1,%2,%3};"
        : "+f"(d[0]), "+f"(d[1]), "+f"(d[2]), "+f"(d[3])
        : "r"(a[0]), "r"(a[1]), "r"(a[2]), "r"(a[3]), "r"(b[0]), "r"(b[1]));
}

// ---------------- prep: xs = fp16(x*scales) ----------------
__global__ void prep_kernel(const float* __restrict__ x, const float* __restrict__ s) {
    int i = blockIdx.x * blockDim.x + threadIdx.x;
    if (i < TOKENS * INF) {
        int k = i & (INF - 1);
        g_xs[i] = __float2half_rn(x[i] * s[k]);
    }
}

// ---------------- main GEMM ----------------
__global__ void __launch_bounds__(NTHR, 4)
qgemm_kernel(const int* __restrict__ W, float* __restrict__ out) {
    __shared__ __align__(1024) char smem[SMEM_TOTAL];
    const uint32_t sb = smem_u32(smem);
    const int tid = threadIdx.x;
    const int lane = tid & 31;
    const int wid = tid >> 5;      // 0..3
    const int rg = wid >> 1;       // row group 0..1 (16 rows each)
    const int th = wid & 1;        // token half 0..1 (16 tokens each)

    const int row_base = blockIdx.x * TILE_M;

    // ---- W producer: base (m0 in 0..15, c0 in 0..7); granules at
    //      row +16 (src +16*INF*4, dst +2048) and k-sub +64 (src +256B, dst +4096)
    const int m0 = tid >> 3;
    const int c0 = tid & 7;
    const char* wpB = (const char*)(W + (size_t)(row_base + m0) * INF + c0 * 8);
    const uint32_t wsts = SWZ(m0 * 128 + c0 * 16);
    static constexpr int W_R = 16 * INF * 4;   // +16 rows (bytes)
    static constexpr int W_S = 64 * 4;         // +64 k elements (bytes)

    // ---- xs producer: same structure over tokens ----
    const char* xpB = (const char*)(g_xs + m0 * INF + c0 * 8);
    const uint32_t xsts = X_OFF + wsts;        // same (t0,c0) -> same swizzled offset
    static constexpr int X_R = 16 * INF * 2;   // +16 tokens (bytes)
    static constexpr int X_S = 64 * 2;         // +64 k elements (bytes)

    // ---- ldmatrix lane geometry ----
    const int rowA  = rg * 16 + (lane & 7) + (lane & 8);
    const int aCsel = (lane & 16);              // +8 fp16 cols -> +16 bytes
    const int tokB  = th * 16 + (lane & 7) + ((lane & 16) >> 1);
    const int bCsel = (lane & 8) * 2;           // +16 bytes for k+8 tile
    const int aOff  = rowA * 128 + aCsel;
    const int bOff  = tokB * 128 + bCsel;

    float acc[2][4];
#pragma unroll
    for (int n = 0; n < 2; n++)
#pragma unroll
        for (int r = 0; r < 4; r++) acc[n][r] = 0.0f;

    // depth-1 W staging: 8 named int4 (granules r0s0,r1s0,r0s1,r1s1 x2)
    int4 w[8];

    // ---- prologue: W chunk 0 -> regs; xs chunk 0 -> cp.async ----
#pragma unroll
    for (int s = 0; s < 2; s++)
#pragma unroll
        for (int r = 0; r < 2; r++) {
            const char* p = wpB + r * W_R + s * W_S;
            w[(s * 2 + r) * 2]     = *(const int4*)(p);
            w[(s * 2 + r) * 2 + 1] = *(const int4*)(p + 16);
        }
    wpB += KC * 4;

#pragma unroll
    for (int s = 0; s < 2; s++)
#pragma unroll
        for (int r = 0; r < 2; r++)
            cp16(sb + xsts + r * 2048 + s * 4096, xpB + r * X_R + s * X_S);
    xpB += KC * 2;
    cp_commit();

#pragma unroll 1
    for (int it = 0; it < NITER; ++it) {
        const uint32_t bufb = sb + (it & 1) * BUF_BYTES;

        // ---- convert + store W tile (readers proven done via sync(it-1)) ----
#pragma unroll
        for (int s = 0; s < 2; s++)
#pragma unroll
            for (int r = 0; r < 2; r++) {
                int4 u = w[(s * 2 + r) * 2], v = w[(s * 2 + r) * 2 + 1];
                sts128(bufb + wsts + r * 2048 + s * 4096,
                       packhf(u.x, u.y), packhf(u.z, u.w),
                       packhf(v.x, v.y), packhf(v.z, v.w));
            }

        // ---- refill stage with chunk it+1 (one full period of cover) ----
        if (it + 1 < NITER) {
#pragma unroll
            for (int s = 0; s < 2; s++)
#pragma unroll
                for (int r = 0; r < 2; r++) {
                    const char* p = wpB + r * W_R + s * W_S;
                    w[(s * 2 + r) * 2]     = *(const int4*)(p);
                    w[(s * 2 + r) * 2 + 1] = *(const int4*)(p + 16);
                }
            wpB += KC * 4;
        }

        cp_wait0();        // xs(it) landed
        __syncthreads();   // tile (it) visible; compute(it-1) done on all warps

        // ---- xs(it+1) cp.async into the other buffer ----
        if (it + 1 < NITER) {
            const uint32_t nb = sb + ((it + 1) & 1) * BUF_BYTES;
#pragma unroll
            for (int s = 0; s < 2; s++)
#pragma unroll
                for (int r = 0; r < 2; r++)
                    cp16(nb + xsts + r * 2048 + s * 4096, xpB + r * X_R + s * X_S);
            xpB += KC * 2;
            cp_commit();
        }

        // ---- compute: 8 k16-steps; per step 1 A-ldsm + 1 B-ldsm + 2 MMA ----
#pragma unroll
        for (int ks = 0; ks < 8; ks++) {
            uint32_t a[4], b[4];
            const int sub = (ks >> 2) * 4096;
            const int kb = (ks & 3) * 32;
            ldsm_x4(bufb + sub + SWZ(aOff + kb), a[0], a[1], a[2], a[3]);
            ldsm_x4(bufb + X_OFF + sub + SWZ(bOff + kb), b[0], b[1], b[2], b[3]);
            mma_16816(acc[0], a, b + 0);
            mma_16816(acc[1], a, b + 2);
        }
    }

    // ---- epilogue: direct stores (no split-K, no atomics) ----
    const int g = lane >> 2;
    const int t2 = (lane & 3) * 2;
    const int f0 = row_base + rg * 16 + g;
#pragma unroll
    for (int nt = 0; nt < 2; nt++) {
        const int tok = th * 16 + nt * 8 + t2;
        out[(size_t)tok * OUTF + f0]           = acc[nt][0];
        out[(size_t)(tok + 1) * OUTF + f0]     = acc[nt][1];
        out[(size_t)tok * OUTF + f0 + 8]       = acc[nt][2];
        out[(size_t)(tok + 1) * OUTF + f0 + 8] = acc[nt][3];
    }
}

// ---------------- launch ----------------
extern "C" void kernel_launch(void* const* d_in, const int* in_sizes, int n_in,
                              void* d_out, int out_size) {
    const float* x      = (const float*)d_in[0];
    const int*   weight = (const int*)d_in[1];
    const float* scales = (const float*)d_in[2];
    float*       out    = (float*)d_out;
    (void)in_sizes; (void)n_in; (void)out_size;

    prep_kernel<<<(TOKENS * INF + 255) / 256, 256>>>(x, scales);
    qgemm_kernel<<<OUTF / TILE_M, NTHR>>>(weight, out);
}